// round 7
// baseline (speedup 1.0000x reference)
#include <cuda_runtime.h>
#include <cuda_bf16.h>
#include <cstdint>
#include <cmath>

// ===========================================================================
// SwinTransformerBlock on GB300 (family-portable PTX path, mma.sync bf16).
// fp32 operands stored as hi/lo bf16 concatenated along K (K'=2K).
// R7: grouped CTA rasterization (GROUP_M=16) in hgemm for L2 reuse of A.
// ===========================================================================

#define MT 131072

__device__ __align__(16) __nv_bfloat16 g_xni [(size_t)MT*512];
__device__ float                       g_qkv [(size_t)MT*768];
__device__ __align__(16) __nv_bfloat16 g_aoi [(size_t)MT*512];
__device__ float                       g_x2  [(size_t)MT*256];
__device__ __align__(16) __nv_bfloat16 g_hidi[(size_t)MT*2048];
__device__ __align__(16) __nv_bfloat16 g_qkvwi[768*512];
__device__ __align__(16) __nv_bfloat16 g_projwi[256*512];
__device__ __align__(16) __nv_bfloat16 g_fc1wi[1024*512];
__device__ __align__(16) __nv_bfloat16 g_fc2wi[256*2048];

// ---------------------------------------------------------------------------
__device__ __forceinline__ uint32_t smem_u32(const void* p) {
    uint32_t a;
    asm("{ .reg .u64 t; cvta.to.shared.u64 t, %1; cvt.u32.u64 %0, t; }" : "=r"(a) : "l"(p));
    return a;
}
#define CP_ASYNC16(sa, ga) \
    asm volatile("cp.async.cg.shared.global [%0], [%1], 16;" :: "r"(sa), "l"(ga))
#define CP_COMMIT() asm volatile("cp.async.commit_group;" ::: "memory")
#define CP_WAIT2()  asm volatile("cp.async.wait_group 2;" ::: "memory")
#define CP_WAIT0()  asm volatile("cp.async.wait_group 0;" ::: "memory")

#define LDSM_X4(r0,r1,r2,r3, a) \
    asm volatile("ldmatrix.sync.aligned.m8n8.x4.shared.b16 {%0,%1,%2,%3}, [%4];" \
        : "=r"(r0), "=r"(r1), "=r"(r2), "=r"(r3) : "r"(a))

#define MMA16816(c, a, b0, b1) \
    asm volatile("mma.sync.aligned.m16n8k16.row.col.f32.bf16.bf16.f32 " \
        "{%0,%1,%2,%3}, {%4,%5,%6,%7}, {%8,%9}, {%0,%1,%2,%3};" \
        : "+f"((c)[0]), "+f"((c)[1]), "+f"((c)[2]), "+f"((c)[3]) \
        : "r"((a)[0]), "r"((a)[1]), "r"((a)[2]), "r"((a)[3]), "r"(b0), "r"(b1))

__device__ __forceinline__ uint32_t pack_bf2(__nv_bfloat16 a, __nv_bfloat16 b) {
    __nv_bfloat162 t = __halves2bfloat162(a, b);
    return *(uint32_t*)&t;
}
__device__ __forceinline__ void store_hilo4(__nv_bfloat16* p_hi, __nv_bfloat16* p_lo, float4 v) {
    __nv_bfloat16 h[4], l[4];
    h[0] = __float2bfloat16(v.x); l[0] = __float2bfloat16(v.x - __bfloat162float(h[0]));
    h[1] = __float2bfloat16(v.y); l[1] = __float2bfloat16(v.y - __bfloat162float(h[1]));
    h[2] = __float2bfloat16(v.z); l[2] = __float2bfloat16(v.z - __bfloat162float(h[2]));
    h[3] = __float2bfloat16(v.w); l[3] = __float2bfloat16(v.w - __bfloat162float(h[3]));
    *(uint2*)p_hi = *(uint2*)h;
    *(uint2*)p_lo = *(uint2*)l;
}
__device__ __forceinline__ float gelu_f(float v) {
    return 0.5f * v * (1.0f + erff(v * 0.7071067811865476f));
}

// ---------------------------------------------------------------------------
// Combined weight conversion: fp32 [N,K] -> hi/lo bf16 [N,2K]
// ---------------------------------------------------------------------------
__global__ void wconv_all(const float* w0, __nv_bfloat16* o0,
                          const float* w1, __nv_bfloat16* o1,
                          const float* w2, __nv_bfloat16* o2,
                          const float* w3, __nv_bfloat16* o3) {
    int i = blockIdx.x * 256 + threadIdx.x;
    const float* w; __nv_bfloat16* o; int K; int li;
    if (i < 49152)        { w = w0; o = o0; K = 256;  li = i; }
    else if (i < 65536)   { w = w1; o = o1; K = 256;  li = i - 49152; }
    else if (i < 131072)  { w = w2; o = o2; K = 256;  li = i - 65536; }
    else if (i < 196608)  { w = w3; o = o3; K = 1024; li = i - 131072; }
    else return;
    int row = li / (K >> 2);
    int c = (li - row * (K >> 2)) * 4;
    float4 v = *(const float4*)(w + (size_t)row * K + c);
    __nv_bfloat16* base = o + (size_t)row * 2 * K;
    store_hilo4(base + c, base + K + c, v);
}

// ---------------------------------------------------------------------------
// LayerNorm (C=256): one warp/row, hi/lo bf16 out [M,512]
// ---------------------------------------------------------------------------
__global__ __launch_bounds__(256) void ln_kernel(
    const float* __restrict__ x, const float* __restrict__ g,
    const float* __restrict__ b, __nv_bfloat16* __restrict__ out)
{
    size_t row = (size_t)blockIdx.x * 8 + (threadIdx.x >> 5);
    int lane = threadIdx.x & 31;
    const float* xr = x + row * 256 + lane * 8;
    float4 v0 = *(const float4*)(xr);
    float4 v1 = *(const float4*)(xr + 4);

    float s  = v0.x+v0.y+v0.z+v0.w + v1.x+v1.y+v1.z+v1.w;
    float sq = v0.x*v0.x+v0.y*v0.y+v0.z*v0.z+v0.w*v0.w
             + v1.x*v1.x+v1.y*v1.y+v1.z*v1.z+v1.w*v1.w;
    #pragma unroll
    for (int o = 16; o > 0; o >>= 1) {
        s  += __shfl_xor_sync(0xffffffffu, s,  o);
        sq += __shfl_xor_sync(0xffffffffu, sq, o);
    }
    float mean = s * (1.0f/256.0f);
    float rstd = rsqrtf(sq * (1.0f/256.0f) - mean*mean + 1e-5f);

    const float4 g0 = *(const float4*)(g + lane*8);
    const float4 g1 = *(const float4*)(g + lane*8 + 4);
    const float4 b0 = *(const float4*)(b + lane*8);
    const float4 b1 = *(const float4*)(b + lane*8 + 4);

    float4 o0, o1;
    o0.x=(v0.x-mean)*rstd*g0.x+b0.x; o0.y=(v0.y-mean)*rstd*g0.y+b0.y;
    o0.z=(v0.z-mean)*rstd*g0.z+b0.z; o0.w=(v0.w-mean)*rstd*g0.w+b0.w;
    o1.x=(v1.x-mean)*rstd*g1.x+b1.x; o1.y=(v1.y-mean)*rstd*g1.y+b1.y;
    o1.z=(v1.z-mean)*rstd*g1.z+b1.z; o1.w=(v1.w-mean)*rstd*g1.w+b1.w;

    int cb = lane * 8;
    __nv_bfloat16* base = out + row * 512;
    store_hilo4(base + cb,     base + 256 + cb,     o0);
    store_hilo4(base + cb + 4, base + 256 + cb + 4, o1);
}

// ---------------------------------------------------------------------------
// bf16 tensor-core GEMM: CTA 128x128, K-chunk 64, 3-stage cp.async pipeline,
// 256 threads (8 warps 4x2), 2 CTAs/SM. Grouped raster (GROUP_M=16) for L2
// reuse of A across N-blocks.
// MODE: 0=bias fp32; 1=bias+res fp32; 2=bias+gelu hi/lo bf16.
// ---------------------------------------------------------------------------
#define HSTAGE 32768
#define HSMEM  (3*HSTAGE)
#define GROUP_M 16

template<int MODE>
__global__ __launch_bounds__(256, 2) void hgemm(
    const __nv_bfloat16* __restrict__ A, const __nv_bfloat16* __restrict__ B,
    const float* __restrict__ bias, const float* __restrict__ res,
    void* __restrict__ Cout, int N, int K2)
{
    extern __shared__ char sm[];
    const uint32_t sbase = smem_u32(sm);
    const int tid  = threadIdx.x;
    const int lane = tid & 31;
    const int warp = tid >> 5;
    const int wr   = warp >> 1;
    const int wc   = warp & 1;

    // grouped raster: M-block fastest within a group of GROUP_M rows
    const int nblk = gridDim.x;
    const int lin  = blockIdx.y * nblk + blockIdx.x;
    const int gsz  = GROUP_M * nblk;
    const int grp  = lin / gsz;
    const int remn = lin - grp * gsz;
    const int m_idx = grp * GROUP_M + (remn % GROUP_M);
    const int n_idx = remn / GROUP_M;

    const size_t gr0 = (size_t)m_idx * 128;
    const int    gc0 = n_idx * 128;
    const int CCH = K2 >> 6;

    const int lrow = tid >> 3;
    const int lkc  = tid & 7;

    auto load_stage = [&](int c) {
        uint32_t sA = sbase + (c % 3) * HSTAGE;
        uint32_t sB = sA + 16384;
        const __nv_bfloat16* Ab = A + c*64 + lkc*8;
        const __nv_bfloat16* Bb = B + c*64 + lkc*8;
        #pragma unroll
        for (int p = 0; p < 4; p++) {
            int row = lrow + p*32;
            uint32_t off = row*128 + (((uint32_t)(lkc ^ (row & 7))) << 4);
            CP_ASYNC16(sA + off, Ab + (gr0 + row) * (size_t)K2);
            CP_ASYNC16(sB + off, Bb + (size_t)(gc0 + row) * K2);
        }
    };

    load_stage(0); CP_COMMIT();
    load_stage(1); CP_COMMIT();

    float acc[2][8][4];
    #pragma unroll
    for (int mt = 0; mt < 2; mt++)
        #pragma unroll
        for (int nt = 0; nt < 8; nt++)
            #pragma unroll
            for (int q = 0; q < 4; q++) acc[mt][nt][q] = 0.0f;

    const int lr8  = (lane & 7) + ((lane >> 3) & 1) * 8;
    const int lkhi = lane >> 4;

    for (int c = 0; c < CCH; c++) {
        if (c + 2 < CCH) { load_stage(c + 2); }
        CP_COMMIT();
        CP_WAIT2();
        __syncthreads();

        uint32_t sA = sbase + (c % 3) * HSTAGE;
        uint32_t sB = sA + 16384;

        #pragma unroll
        for (int ks = 0; ks < 4; ks++) {
            uint32_t a[2][4];
            #pragma unroll
            for (int mt = 0; mt < 2; mt++) {
                int row = wr*32 + mt*16 + lr8;
                int kc  = 2*ks + lkhi;
                LDSM_X4(a[mt][0], a[mt][1], a[mt][2], a[mt][3],
                        sA + row*128 + ((uint32_t)(kc ^ (row & 7)) << 4));
            }
            uint32_t b[4][4];
            #pragma unroll
            for (int nq = 0; nq < 4; nq++) {
                int row = wc*64 + nq*16 + lr8;
                int kc  = 2*ks + lkhi;
                LDSM_X4(b[nq][0], b[nq][1], b[nq][2], b[nq][3],
                        sB + row*128 + ((uint32_t)(kc ^ (row & 7)) << 4));
            }
            #pragma unroll
            for (int mt = 0; mt < 2; mt++)
                #pragma unroll
                for (int nt = 0; nt < 8; nt++)
                    MMA16816(acc[mt][nt], a[mt], b[nt>>1][nt&1], b[nt>>1][2+(nt&1)]);
        }
        __syncthreads();
    }

    // epilogue: stage through smem, coalesced stores
    CP_WAIT0();
    float* epi = (float*)sm;
    const int mrow = lane >> 2;
    const int ncol = (lane & 3) * 2;
    #pragma unroll
    for (int mt = 0; mt < 2; mt++)
        #pragma unroll
        for (int half = 0; half < 2; half++) {
            int r = wr*32 + mt*16 + half*8 + mrow;
            #pragma unroll
            for (int nt = 0; nt < 8; nt++) {
                int cc = wc*64 + nt*8 + ncol;
                *(float2*)&epi[r*132 + cc] =
                    make_float2(acc[mt][nt][half*2], acc[mt][nt][half*2+1]);
            }
        }
    __syncthreads();

    #pragma unroll 4
    for (int it = 0; it < 16; it++) {
        int idx = it*256 + tid;
        int row = idx >> 5;
        int c4  = (idx & 31) * 4;
        int gcol = gc0 + c4;
        float4 v = *(float4*)&epi[row*132 + c4];
        float4 bb = *(const float4*)(bias + gcol);
        v.x += bb.x; v.y += bb.y; v.z += bb.z; v.w += bb.w;
        size_t grow = gr0 + row;
        if (MODE == 1) {
            float4 r = *(const float4*)(res + grow * (size_t)N + gcol);
            v.x += r.x; v.y += r.y; v.z += r.z; v.w += r.w;
        }
        if (MODE == 2) {
            v.x = gelu_f(v.x); v.y = gelu_f(v.y); v.z = gelu_f(v.z); v.w = gelu_f(v.w);
            __nv_bfloat16* base = (__nv_bfloat16*)Cout + grow * (size_t)(2*N);
            store_hilo4(base + gcol, base + N + gcol, v);
        } else {
            *(float4*)((float*)Cout + grow * (size_t)N + gcol) = v;
        }
    }
}

// ---------------------------------------------------------------------------
// Fused shifted-window attention via mma.sync. One block per (window, head),
// 128 threads (4 warps). Scores K'=64; p@v K'=128. In-register softmax.
// ---------------------------------------------------------------------------
__global__ __launch_bounds__(128) void attn_kernel(
    const float* __restrict__ qkv, const float* __restrict__ mask,
    const float* __restrict__ bt, __nv_bfloat16* __restrict__ aoi)
{
    __shared__ __align__(16) __nv_bfloat16 q_s[64*64];
    __shared__ __align__(16) __nv_bfloat16 k_s[64*64];
    __shared__ __align__(16) __nv_bfloat16 v_s[32*128];
    __shared__ __align__(16) __nv_bfloat16 p_s[64*128];
    __shared__ float sv[64*34];

    const int head = blockIdx.x;
    const int w    = blockIdx.y;
    const int bimg = w >> 8;
    const int wimg = w & 255;
    const int wh   = wimg >> 4;
    const int ww   = wimg & 15;
    const int tid  = threadIdx.x;
    const int lane = tid & 31;
    const int wp   = tid >> 5;
    const uint32_t qb = smem_u32(q_s), kb = smem_u32(k_s),
                   vb = smem_u32(v_s), pb = smem_u32(p_s);
    const float scale = 0.17677669529663689f;

    // ---- gather + convert q,k (scale folded into q); stage v fp32 ----
    {
        const int dp = (tid & 15) * 2;
        const uint32_t wi  = (dp*2) & 15;
        const uint32_t ch  = dp >> 3;
        #pragma unroll
        for (int it = 0; it < 8; it++) {
            int r = (tid >> 4) + 8*it;
            int i = r >> 3, j = r & 7;
            int oh = (wh*8 + i + 4) & 127;
            int ow = (ww*8 + j + 4) & 127;
            size_t tok = (size_t)bimg*16384 + oh*128 + ow;
            const float* src = qkv + tok*768 + head*32 + dp;
            float2 qv = *(const float2*)(src);
            float2 kv = *(const float2*)(src + 256);
            float2 vv = *(const float2*)(src + 512);
            qv.x *= scale; qv.y *= scale;
            __nv_bfloat16 qh0=__float2bfloat16(qv.x), qh1=__float2bfloat16(qv.y);
            __nv_bfloat16 ql0=__float2bfloat16(qv.x-__bfloat162float(qh0));
            __nv_bfloat16 ql1=__float2bfloat16(qv.y-__bfloat162float(qh1));
            __nv_bfloat16 kh0=__float2bfloat16(kv.x), kh1=__float2bfloat16(kv.y);
            __nv_bfloat16 kl0=__float2bfloat16(kv.x-__bfloat162float(kh0));
            __nv_bfloat16 kl1=__float2bfloat16(kv.y-__bfloat162float(kh1));
            uint32_t hia = r*128 + ((ch ^ (uint32_t)(r&7))<<4) + wi;
            uint32_t loa = r*128 + (((ch+4) ^ (uint32_t)(r&7))<<4) + wi;
            *(uint32_t*)((char*)q_s + hia) = pack_bf2(qh0, qh1);
            *(uint32_t*)((char*)q_s + loa) = pack_bf2(ql0, ql1);
            *(uint32_t*)((char*)k_s + hia) = pack_bf2(kh0, kh1);
            *(uint32_t*)((char*)k_s + loa) = pack_bf2(kl0, kl1);
            *(float2*)&sv[r*34 + dp] = vv;
        }
    }
    __syncthreads();

    // ---- transpose-convert v into v_s[dd][m hi/lo] ----
    {
        const int dd = tid & 31;
        const int mg = tid >> 5;
        #pragma unroll
        for (int i = 0; i < 16; i++) {
            int m = mg*16 + i;
            float x = sv[m*34 + dd];
            __nv_bfloat16 h = __float2bfloat16(x);
            __nv_bfloat16 l = __float2bfloat16(x - __bfloat162float(h));
            uint32_t wi = (m*2) & 15;
            uint32_t hia = dd*256 + ((uint32_t)((m>>3)     ^ (dd&7))<<4) + wi;
            uint32_t loa = dd*256 + ((uint32_t)((8+(m>>3)) ^ (dd&7))<<4) + wi;
            *(__nv_bfloat16*)((char*)v_s + hia) = h;
            *(__nv_bfloat16*)((char*)v_s + loa) = l;
        }
    }
    __syncthreads();

    const int lr8  = (lane & 7) + ((lane >> 3) & 1) * 8;
    const int lkhi = lane >> 4;

    // ---- scores ----
    float acc[8][4];
    #pragma unroll
    for (int nt = 0; nt < 8; nt++)
        #pragma unroll
        for (int q = 0; q < 4; q++) acc[nt][q] = 0.0f;

    #pragma unroll
    for (int ks = 0; ks < 4; ks++) {
        int arow = wp*16 + lr8;
        int kc   = 2*ks + lkhi;
        uint32_t a[4];
        LDSM_X4(a[0], a[1], a[2], a[3],
                qb + arow*128 + ((uint32_t)(kc ^ (arow & 7)) << 4));
        uint32_t b[4][4];
        #pragma unroll
        for (int nq = 0; nq < 4; nq++) {
            int brow = nq*16 + lr8;
            LDSM_X4(b[nq][0], b[nq][1], b[nq][2], b[nq][3],
                    kb + brow*128 + ((uint32_t)(kc ^ (brow & 7)) << 4));
        }
        #pragma unroll
        for (int nt = 0; nt < 8; nt++)
            MMA16816(acc[nt], a, b[nt>>1][nt&1], b[nt>>1][2+(nt&1)]);
    }

    // ---- bias + mask + softmax ----
    const int r0 = wp*16 + (lane >> 2);
    const int r1 = r0 + 8;
    const float* mrow = mask + (size_t)wimg * 4096;
    float mx0 = -1e30f, mx1 = -1e30f;
    #pragma unroll
    for (int nt = 0; nt < 8; nt++) {
        #pragma unroll
        for (int e = 0; e < 2; e++) {
            int m = nt*8 + (lane & 3)*2 + e;
            int ri0 = ((r0>>3) - (m>>3) + 7)*15 + ((r0&7) - (m&7) + 7);
            int ri1 = ((r1>>3) - (m>>3) + 7)*15 + ((r1&7) - (m&7) + 7);
            acc[nt][e]   += bt[ri0*8 + head] + mrow[r0*64 + m];
            acc[nt][2+e] += bt[ri1*8 + head] + mrow[r1*64 + m];
            mx0 = fmaxf(mx0, acc[nt][e]);
            mx1 = fmaxf(mx1, acc[nt][2+e]);
        }
    }
    mx0 = fmaxf(mx0, __shfl_xor_sync(0xffffffffu, mx0, 1));
    mx0 = fmaxf(mx0, __shfl_xor_sync(0xffffffffu, mx0, 2));
    mx1 = fmaxf(mx1, __shfl_xor_sync(0xffffffffu, mx1, 1));
    mx1 = fmaxf(mx1, __shfl_xor_sync(0xffffffffu, mx1, 2));
    float s0 = 0.0f, s1 = 0.0f;
    #pragma unroll
    for (int nt = 0; nt < 8; nt++) {
        #pragma unroll
        for (int e = 0; e < 2; e++) {
            acc[nt][e]   = __expf(acc[nt][e]   - mx0); s0 += acc[nt][e];
            acc[nt][2+e] = __expf(acc[nt][2+e] - mx1); s1 += acc[nt][2+e];
        }
    }
    s0 += __shfl_xor_sync(0xffffffffu, s0, 1);
    s0 += __shfl_xor_sync(0xffffffffu, s0, 2);
    s1 += __shfl_xor_sync(0xffffffffu, s1, 1);
    s1 += __shfl_xor_sync(0xffffffffu, s1, 2);
    float inv0 = 1.0f / s0, inv1 = 1.0f / s1;

    // ---- write p (hi/lo bf16) into p_s ----
    #pragma unroll
    for (int nt = 0; nt < 8; nt++) {
        int c = nt*8 + (lane & 3)*2;
        float p0 = acc[nt][0]*inv0, p1 = acc[nt][1]*inv0;
        float p2 = acc[nt][2]*inv1, p3 = acc[nt][3]*inv1;
        __nv_bfloat16 h0=__float2bfloat16(p0), h1=__float2bfloat16(p1);
        __nv_bfloat16 l0=__float2bfloat16(p0-__bfloat162float(h0));
        __nv_bfloat16 l1=__float2bfloat16(p1-__bfloat162float(h1));
        __nv_bfloat16 h2=__float2bfloat16(p2), h3=__float2bfloat16(p3);
        __nv_bfloat16 l2=__float2bfloat16(p2-__bfloat162float(h2));
        __nv_bfloat16 l3=__float2bfloat16(p3-__bfloat162float(h3));
        uint32_t wi = (uint32_t)(c*2) & 15;
        uint32_t hi0 = r0*256 + ((uint32_t)(nt     ^ (r0&7))<<4) + wi;
        uint32_t lo0 = r0*256 + ((uint32_t)((8+nt) ^ (r0&7))<<4) + wi;
        uint32_t hi1 = r1*256 + ((uint32_t)(nt     ^ (r1&7))<<4) + wi;
        uint32_t lo1 = r1*256 + ((uint32_t)((8+nt) ^ (r1&7))<<4) + wi;
        *(uint32_t*)((char*)p_s + hi0) = pack_bf2(h0, h1);
        *(uint32_t*)((char*)p_s + lo0) = pack_bf2(l0, l1);
        *(uint32_t*)((char*)p_s + hi1) = pack_bf2(h2, h3);
        *(uint32_t*)((char*)p_s + lo1) = pack_bf2(l2, l3);
    }
    __syncwarp();

    // ---- out = p @ v ----
    float o[4][4];
    #pragma unroll
    for (int nt = 0; nt < 4; nt++)
        #pragma unroll
        for (int q = 0; q < 4; q++) o[nt][q] = 0.0f;

    #pragma unroll
    for (int ks = 0; ks < 8; ks++) {
        int arow = wp*16 + lr8;
        int kc   = 2*ks + lkhi;
        uint32_t a[4];
        LDSM_X4(a[0], a[1], a[2], a[3],
                pb + arow*256 + ((uint32_t)(kc ^ (arow & 7)) << 4));
        uint32_t b[2][4];
        #pragma unroll
        for (int nq = 0; nq < 2; nq++) {
            int brow = nq*16 + lr8;
            LDSM_X4(b[nq][0], b[nq][1], b[nq][2], b[nq][3],
                    vb + brow*256 + ((uint32_t)(kc ^ (brow & 7)) << 4));
        }
        #pragma unroll
        for (int nt = 0; nt < 4; nt++)
            MMA16816(o[nt], a, b[nt>>1][nt&1], b[nt>>1][2+(nt&1)]);
    }

    // ---- scatter out (hi/lo bf16) ----
    #pragma unroll
    for (int s = 0; s < 2; s++) {
        int n = s ? r1 : r0;
        int i = n >> 3, j = n & 7;
        int oh = (wh*8 + i + 4) & 127;
        int ow = (ww*8 + j + 4) & 127;
        size_t tok = (size_t)bimg*16384 + oh*128 + ow;
        __nv_bfloat16* base = aoi + tok*512 + head*32;
        #pragma unroll
        for (int nt = 0; nt < 4; nt++) {
            int c = nt*8 + (lane & 3)*2;
            float v0 = o[nt][s*2], v1 = o[nt][s*2+1];
            __nv_bfloat16 h0=__float2bfloat16(v0), h1=__float2bfloat16(v1);
            __nv_bfloat16 l0=__float2bfloat16(v0-__bfloat162float(h0));
            __nv_bfloat16 l1=__float2bfloat16(v1-__bfloat162float(h1));
            *(uint32_t*)(base + c)       = pack_bf2(h0, h1);
            *(uint32_t*)(base + 256 + c) = pack_bf2(l0, l1);
        }
    }
}

// ---------------------------------------------------------------------------
extern "C" void kernel_launch(void* const* d_in, const int* in_sizes, int n_in,
                              void* d_out, int out_size)
{
    const float* x     = (const float*)d_in[0];
    const float* mask  = (const float*)d_in[1];
    const float* n1g   = (const float*)d_in[2];
    const float* n1b   = (const float*)d_in[3];
    const float* qkvw  = (const float*)d_in[4];
    const float* qkvb  = (const float*)d_in[5];
    const float* relb  = (const float*)d_in[6];
    const float* projw = (const float*)d_in[7];
    const float* projb = (const float*)d_in[8];
    const float* n2g   = (const float*)d_in[9];
    const float* n2b   = (const float*)d_in[10];
    const float* fc1w  = (const float*)d_in[11];
    const float* fc1b  = (const float*)d_in[12];
    const float* fc2w  = (const float*)d_in[13];
    const float* fc2b  = (const float*)d_in[14];
    float* out = (float*)d_out;

    __nv_bfloat16 *xni, *aoi, *hidi, *qkvwi, *projwi, *fc1wi, *fc2wi;
    float *qkv, *x2;
    cudaGetSymbolAddress((void**)&xni,   g_xni);
    cudaGetSymbolAddress((void**)&qkv,   g_qkv);
    cudaGetSymbolAddress((void**)&aoi,   g_aoi);
    cudaGetSymbolAddress((void**)&x2,    g_x2);
    cudaGetSymbolAddress((void**)&hidi,  g_hidi);
    cudaGetSymbolAddress((void**)&qkvwi, g_qkvwi);
    cudaGetSymbolAddress((void**)&projwi,g_projwi);
    cudaGetSymbolAddress((void**)&fc1wi, g_fc1wi);
    cudaGetSymbolAddress((void**)&fc2wi, g_fc2wi);

    cudaFuncSetAttribute(hgemm<0>, cudaFuncAttributeMaxDynamicSharedMemorySize, HSMEM);
    cudaFuncSetAttribute(hgemm<1>, cudaFuncAttributeMaxDynamicSharedMemorySize, HSMEM);
    cudaFuncSetAttribute(hgemm<2>, cudaFuncAttributeMaxDynamicSharedMemorySize, HSMEM);

    wconv_all<<<768, 256>>>(qkvw, qkvwi, projw, projwi, fc1w, fc1wi, fc2w, fc2wi);

    // 1. LN1
    ln_kernel<<<MT/8, 256>>>(x, n1g, n1b, xni);
    // 2. QKV: [131072,512] @ [768,512]^T -> fp32
    hgemm<0><<<dim3(6, MT/128), 256, HSMEM>>>(xni, qkvwi, qkvb, nullptr, qkv, 768, 512);
    // 3. windowed attention (tensor-core)
    attn_kernel<<<dim3(8, 2048), 128>>>(qkv, mask, relb, aoi);
    // 4. proj + residual(x) -> x2
    hgemm<1><<<dim3(2, MT/128), 256, HSMEM>>>(aoi, projwi, projb, x, x2, 256, 512);
    // 5. LN2
    ln_kernel<<<MT/8, 256>>>(x2, n2g, n2b, xni);
    // 6. FC1 + gelu -> hidden (hi/lo bf16)
    hgemm<2><<<dim3(8, MT/128), 256, HSMEM>>>(xni, fc1wi, fc1b, nullptr, hidi, 1024, 512);
    // 7. FC2 + residual(x2) -> out
    hgemm<1><<<dim3(2, MT/128), 256, HSMEM>>>(hidi, fc2wi, fc2b, x2, out, 256, 2048);
}

// round 8
// speedup vs baseline: 1.6337x; 1.6337x over previous
#include <cuda_runtime.h>
#include <cuda_fp16.h>
#include <cstdint>
#include <cmath>

// ===========================================================================
// SwinTransformerBlock on GB300 (family-portable PTX, mma.sync fp16).
// R8: all GEMM/attention operands single fp16 (K'=K). fp16 per-element
// rounding (2^-11) is ~4x smaller than the previous hi/lo-bf16 scheme's
// dropped cross terms (2^-9), at HALF the MMA work and HALF the traffic.
// ===========================================================================

#define MT 131072

__device__ __align__(16) __half g_xni [(size_t)MT*256];   // LN out fp16
__device__ __align__(16) __half g_qkv [(size_t)MT*768];   // qkv fp16
__device__ __align__(16) __half g_aoi [(size_t)MT*256];   // attn out fp16
__device__ float                g_x2  [(size_t)MT*256];   // residual-1 fp32
__device__ __align__(16) __half g_hidi[(size_t)MT*1024];  // hidden fp16
__device__ __align__(16) __half g_qkvwi[768*256];
__device__ __align__(16) __half g_projwi[256*256];
__device__ __align__(16) __half g_fc1wi[1024*256];
__device__ __align__(16) __half g_fc2wi[256*1024];

// ---------------------------------------------------------------------------
__device__ __forceinline__ uint32_t smem_u32(const void* p) {
    uint32_t a;
    asm("{ .reg .u64 t; cvta.to.shared.u64 t, %1; cvt.u32.u64 %0, t; }" : "=r"(a) : "l"(p));
    return a;
}
#define CP_ASYNC16(sa, ga) \
    asm volatile("cp.async.cg.shared.global [%0], [%1], 16;" :: "r"(sa), "l"(ga))
#define CP_COMMIT() asm volatile("cp.async.commit_group;" ::: "memory")
#define CP_WAIT2()  asm volatile("cp.async.wait_group 2;" ::: "memory")
#define CP_WAIT0()  asm volatile("cp.async.wait_group 0;" ::: "memory")

#define LDSM_X4(r0,r1,r2,r3, a) \
    asm volatile("ldmatrix.sync.aligned.m8n8.x4.shared.b16 {%0,%1,%2,%3}, [%4];" \
        : "=r"(r0), "=r"(r1), "=r"(r2), "=r"(r3) : "r"(a))

#define MMA16816(c, a, b0, b1) \
    asm volatile("mma.sync.aligned.m16n8k16.row.col.f32.f16.f16.f32 " \
        "{%0,%1,%2,%3}, {%4,%5,%6,%7}, {%8,%9}, {%0,%1,%2,%3};" \
        : "+f"((c)[0]), "+f"((c)[1]), "+f"((c)[2]), "+f"((c)[3]) \
        : "r"((a)[0]), "r"((a)[1]), "r"((a)[2]), "r"((a)[3]), "r"(b0), "r"(b1))

__device__ __forceinline__ uint32_t pack_h2(float a, float b) {
    __half2 t = __floats2half2_rn(a, b);
    return *(uint32_t*)&t;
}
__device__ __forceinline__ uint2 pack_h4(float4 v) {
    uint2 u;
    u.x = pack_h2(v.x, v.y);
    u.y = pack_h2(v.z, v.w);
    return u;
}
__device__ __forceinline__ float gelu_f(float v) {
    return 0.5f * v * (1.0f + erff(v * 0.7071067811865476f));
}

// ---------------------------------------------------------------------------
// Combined weight conversion: fp32 [N,K] -> fp16 [N,K]
// ---------------------------------------------------------------------------
__global__ void wconv_all(const float* w0, __half* o0,
                          const float* w1, __half* o1,
                          const float* w2, __half* o2,
                          const float* w3, __half* o3) {
    int i = blockIdx.x * 256 + threadIdx.x;
    const float* w; __half* o; int li;
    if (i < 49152)        { w = w0; o = o0; li = i; }
    else if (i < 65536)   { w = w1; o = o1; li = i - 49152; }
    else if (i < 131072)  { w = w2; o = o2; li = i - 65536; }
    else if (i < 196608)  { w = w3; o = o3; li = i - 131072; }
    else return;
    float4 v = *(const float4*)(w + (size_t)li * 4);
    *(uint2*)(o + (size_t)li * 4) = pack_h4(v);
}

// ---------------------------------------------------------------------------
// LayerNorm (C=256): one warp/row, fp16 out [M,256]
// ---------------------------------------------------------------------------
__global__ __launch_bounds__(256) void ln_kernel(
    const float* __restrict__ x, const float* __restrict__ g,
    const float* __restrict__ b, __half* __restrict__ out)
{
    size_t row = (size_t)blockIdx.x * 8 + (threadIdx.x >> 5);
    int lane = threadIdx.x & 31;
    const float* xr = x + row * 256 + lane * 8;
    float4 v0 = *(const float4*)(xr);
    float4 v1 = *(const float4*)(xr + 4);

    float s  = v0.x+v0.y+v0.z+v0.w + v1.x+v1.y+v1.z+v1.w;
    float sq = v0.x*v0.x+v0.y*v0.y+v0.z*v0.z+v0.w*v0.w
             + v1.x*v1.x+v1.y*v1.y+v1.z*v1.z+v1.w*v1.w;
    #pragma unroll
    for (int o = 16; o > 0; o >>= 1) {
        s  += __shfl_xor_sync(0xffffffffu, s,  o);
        sq += __shfl_xor_sync(0xffffffffu, sq, o);
    }
    float mean = s * (1.0f/256.0f);
    float rstd = rsqrtf(sq * (1.0f/256.0f) - mean*mean + 1e-5f);

    const float4 g0 = *(const float4*)(g + lane*8);
    const float4 g1 = *(const float4*)(g + lane*8 + 4);
    const float4 b0 = *(const float4*)(b + lane*8);
    const float4 b1 = *(const float4*)(b + lane*8 + 4);

    float4 o0, o1;
    o0.x=(v0.x-mean)*rstd*g0.x+b0.x; o0.y=(v0.y-mean)*rstd*g0.y+b0.y;
    o0.z=(v0.z-mean)*rstd*g0.z+b0.z; o0.w=(v0.w-mean)*rstd*g0.w+b0.w;
    o1.x=(v1.x-mean)*rstd*g1.x+b1.x; o1.y=(v1.y-mean)*rstd*g1.y+b1.y;
    o1.z=(v1.z-mean)*rstd*g1.z+b1.z; o1.w=(v1.w-mean)*rstd*g1.w+b1.w;

    uint4 u;
    u.x = pack_h2(o0.x, o0.y); u.y = pack_h2(o0.z, o0.w);
    u.z = pack_h2(o1.x, o1.y); u.w = pack_h2(o1.z, o1.w);
    *(uint4*)(out + row * 256 + lane * 8) = u;
}

// ---------------------------------------------------------------------------
// fp16 tensor-core GEMM: CTA 128x128, K-chunk 64, 3-stage cp.async pipeline,
// 256 threads (8 warps 4x2), 2 CTAs/SM.
// MODE: 0=bias fp32; 1=bias+res fp32; 2=bias+gelu fp16; 3=bias fp16.
// ---------------------------------------------------------------------------
#define HSTAGE 32768
#define HSMEM  (3*HSTAGE)

template<int MODE>
__global__ __launch_bounds__(256, 2) void hgemm(
    const __half* __restrict__ A, const __half* __restrict__ B,
    const float* __restrict__ bias, const float* __restrict__ res,
    void* __restrict__ Cout, int N, int K)
{
    extern __shared__ char sm[];
    const uint32_t sbase = smem_u32(sm);
    const int tid  = threadIdx.x;
    const int lane = tid & 31;
    const int warp = tid >> 5;
    const int wr   = warp >> 1;
    const int wc   = warp & 1;
    const size_t gr0 = (size_t)blockIdx.y * 128;
    const int    gc0 = blockIdx.x * 128;
    const int CCH = K >> 6;

    const int lrow = tid >> 3;
    const int lkc  = tid & 7;

    auto load_stage = [&](int c) {
        uint32_t sA = sbase + (c % 3) * HSTAGE;
        uint32_t sB = sA + 16384;
        const __half* Ab = A + c*64 + lkc*8;
        const __half* Bb = B + c*64 + lkc*8;
        #pragma unroll
        for (int p = 0; p < 4; p++) {
            int row = lrow + p*32;
            uint32_t off = row*128 + (((uint32_t)(lkc ^ (row & 7))) << 4);
            CP_ASYNC16(sA + off, Ab + (gr0 + row) * (size_t)K);
            CP_ASYNC16(sB + off, Bb + (size_t)(gc0 + row) * K);
        }
    };

    load_stage(0); CP_COMMIT();
    load_stage(1); CP_COMMIT();

    float acc[2][8][4];
    #pragma unroll
    for (int mt = 0; mt < 2; mt++)
        #pragma unroll
        for (int nt = 0; nt < 8; nt++)
            #pragma unroll
            for (int q = 0; q < 4; q++) acc[mt][nt][q] = 0.0f;

    const int lr8  = (lane & 7) + ((lane >> 3) & 1) * 8;
    const int lkhi = lane >> 4;

    for (int c = 0; c < CCH; c++) {
        if (c + 2 < CCH) { load_stage(c + 2); }
        CP_COMMIT();
        CP_WAIT2();
        __syncthreads();

        uint32_t sA = sbase + (c % 3) * HSTAGE;
        uint32_t sB = sA + 16384;

        #pragma unroll
        for (int ks = 0; ks < 4; ks++) {
            uint32_t a[2][4];
            #pragma unroll
            for (int mt = 0; mt < 2; mt++) {
                int row = wr*32 + mt*16 + lr8;
                int kc  = 2*ks + lkhi;
                LDSM_X4(a[mt][0], a[mt][1], a[mt][2], a[mt][3],
                        sA + row*128 + ((uint32_t)(kc ^ (row & 7)) << 4));
            }
            uint32_t b[4][4];
            #pragma unroll
            for (int nq = 0; nq < 4; nq++) {
                int row = wc*64 + nq*16 + lr8;
                int kc  = 2*ks + lkhi;
                LDSM_X4(b[nq][0], b[nq][1], b[nq][2], b[nq][3],
                        sB + row*128 + ((uint32_t)(kc ^ (row & 7)) << 4));
            }
            #pragma unroll
            for (int mt = 0; mt < 2; mt++)
                #pragma unroll
                for (int nt = 0; nt < 8; nt++)
                    MMA16816(acc[mt][nt], a[mt], b[nt>>1][nt&1], b[nt>>1][2+(nt&1)]);
        }
        __syncthreads();
    }

    // epilogue: stage through smem, coalesced stores
    CP_WAIT0();
    float* epi = (float*)sm;
    const int mrow = lane >> 2;
    const int ncol = (lane & 3) * 2;
    #pragma unroll
    for (int mt = 0; mt < 2; mt++)
        #pragma unroll
        for (int half = 0; half < 2; half++) {
            int r = wr*32 + mt*16 + half*8 + mrow;
            #pragma unroll
            for (int nt = 0; nt < 8; nt++) {
                int cc = wc*64 + nt*8 + ncol;
                *(float2*)&epi[r*132 + cc] =
                    make_float2(acc[mt][nt][half*2], acc[mt][nt][half*2+1]);
            }
        }
    __syncthreads();

    #pragma unroll 4
    for (int it = 0; it < 16; it++) {
        int idx = it*256 + tid;
        int row = idx >> 5;
        int c4  = (idx & 31) * 4;
        int gcol = gc0 + c4;
        float4 v = *(float4*)&epi[row*132 + c4];
        float4 bb = *(const float4*)(bias + gcol);
        v.x += bb.x; v.y += bb.y; v.z += bb.z; v.w += bb.w;
        size_t grow = gr0 + row;
        if (MODE == 1) {
            float4 r = *(const float4*)(res + grow * (size_t)N + gcol);
            v.x += r.x; v.y += r.y; v.z += r.z; v.w += r.w;
        }
        if (MODE == 2) {
            v.x = gelu_f(v.x); v.y = gelu_f(v.y); v.z = gelu_f(v.z); v.w = gelu_f(v.w);
        }
        if (MODE == 2 || MODE == 3) {
            *(uint2*)((__half*)Cout + grow * (size_t)N + gcol) = pack_h4(v);
        } else {
            *(float4*)((float*)Cout + grow * (size_t)N + gcol) = v;
        }
    }
}

// ---------------------------------------------------------------------------
// Fused shifted-window attention via mma.sync fp16. One block per
// (window, head), 128 threads (4 warps). Scores K=32; p@v K=64.
// qk_s row layout (128B): chunks 0-3 = q[d 0..31], chunks 4-7 = k[d 0..31].
// ---------------------------------------------------------------------------
__global__ __launch_bounds__(128) void attn_kernel(
    const __half* __restrict__ qkv, const float* __restrict__ mask,
    const float* __restrict__ bt, __half* __restrict__ aoi)
{
    __shared__ __align__(16) __half qk_s[64*64];   // 8 KB
    __shared__ __align__(16) __half v_s[32*64];    // 4 KB [dd][m]
    __shared__ __align__(16) __half p_s[64*64];    // 8 KB [n][m]
    __shared__ float sv[64*34];                    // fp32 v staging

    const int head = blockIdx.x;
    const int w    = blockIdx.y;
    const int bimg = w >> 8;
    const int wimg = w & 255;
    const int wh   = wimg >> 4;
    const int ww   = wimg & 15;
    const int tid  = threadIdx.x;
    const int lane = tid & 31;
    const int wp   = tid >> 5;
    const uint32_t qkb = smem_u32(qk_s), vb = smem_u32(v_s), pb = smem_u32(p_s);
    const float scale = 0.17677669529663689f;

    // ---- gather q,k (fp16 copy; scale folded into q), stage v ----
    {
        const int dp = (tid & 15) * 2;          // d pair
        const uint32_t ch = dp >> 3;            // logical chunk 0..3
        const uint32_t wi = (dp & 7) * 2;       // byte offset in chunk
        #pragma unroll
        for (int it = 0; it < 8; it++) {
            int r = (tid >> 4) + 8*it;
            int i = r >> 3, j = r & 7;
            int oh = (wh*8 + i + 4) & 127;
            int ow = (ww*8 + j + 4) & 127;
            size_t tok = (size_t)bimg*16384 + oh*128 + ow;
            const __half* src = qkv + tok*768 + head*32 + dp;
            __half2 qh = *(const __half2*)(src);
            __half2 kh = *(const __half2*)(src + 256);
            __half2 vh = *(const __half2*)(src + 512);
            float2 qf = __half22float2(qh);
            uint32_t qp = pack_h2(qf.x * scale, qf.y * scale);
            uint32_t qa = r*128 + ((ch ^ (uint32_t)(r&7))<<4) + wi;
            uint32_t ka = r*128 + (((ch+4) ^ (uint32_t)(r&7))<<4) + wi;
            *(uint32_t*)((char*)qk_s + qa) = qp;
            *(uint32_t*)((char*)qk_s + ka) = *(uint32_t*)&kh;
            float2 vf = __half22float2(vh);
            *(float2*)&sv[r*34 + dp] = vf;
        }
    }
    __syncthreads();

    // ---- transpose v into v_s[dd][m] fp16 ----
    {
        const int dd = tid & 31;
        const int mg = tid >> 5;
        #pragma unroll
        for (int i = 0; i < 16; i++) {
            int m = mg*16 + i;
            float x = sv[m*34 + dd];
            uint32_t a = dd*128 + ((uint32_t)((m>>3) ^ (dd&7))<<4) + (m&7)*2;
            *(__half*)((char*)v_s + a) = __float2half_rn(x);
        }
    }
    __syncthreads();

    const int lr8  = (lane & 7) + ((lane >> 3) & 1) * 8;
    const int lkhi = lane >> 4;

    // ---- scores: warp wp rows [16wp,16wp+16) x 64, K=32 (2 ks-steps) ----
    float acc[8][4];
    #pragma unroll
    for (int nt = 0; nt < 8; nt++)
        #pragma unroll
        for (int q = 0; q < 4; q++) acc[nt][q] = 0.0f;

    #pragma unroll
    for (int ks = 0; ks < 2; ks++) {
        int arow = wp*16 + lr8;
        int kcq  = 2*ks + lkhi;          // q chunks 0..3
        uint32_t a[4];
        LDSM_X4(a[0], a[1], a[2], a[3],
                qkb + arow*128 + ((uint32_t)(kcq ^ (arow & 7)) << 4));
        uint32_t b[4][4];
        #pragma unroll
        for (int nq = 0; nq < 4; nq++) {
            int brow = nq*16 + lr8;
            int kck  = 4 + 2*ks + lkhi;  // k chunks 4..7
            LDSM_X4(b[nq][0], b[nq][1], b[nq][2], b[nq][3],
                    qkb + brow*128 + ((uint32_t)(kck ^ (brow & 7)) << 4));
        }
        #pragma unroll
        for (int nt = 0; nt < 8; nt++)
            MMA16816(acc[nt], a, b[nt>>1][nt&1], b[nt>>1][2+(nt&1)]);
    }

    // ---- bias + mask + softmax (in-register) ----
    const int r0 = wp*16 + (lane >> 2);
    const int r1 = r0 + 8;
    const float* mrow = mask + (size_t)wimg * 4096;
    float mx0 = -1e30f, mx1 = -1e30f;
    #pragma unroll
    for (int nt = 0; nt < 8; nt++) {
        #pragma unroll
        for (int e = 0; e < 2; e++) {
            int m = nt*8 + (lane & 3)*2 + e;
            int ri0 = ((r0>>3) - (m>>3) + 7)*15 + ((r0&7) - (m&7) + 7);
            int ri1 = ((r1>>3) - (m>>3) + 7)*15 + ((r1&7) - (m&7) + 7);
            acc[nt][e]   += bt[ri0*8 + head] + mrow[r0*64 + m];
            acc[nt][2+e] += bt[ri1*8 + head] + mrow[r1*64 + m];
            mx0 = fmaxf(mx0, acc[nt][e]);
            mx1 = fmaxf(mx1, acc[nt][2+e]);
        }
    }
    mx0 = fmaxf(mx0, __shfl_xor_sync(0xffffffffu, mx0, 1));
    mx0 = fmaxf(mx0, __shfl_xor_sync(0xffffffffu, mx0, 2));
    mx1 = fmaxf(mx1, __shfl_xor_sync(0xffffffffu, mx1, 1));
    mx1 = fmaxf(mx1, __shfl_xor_sync(0xffffffffu, mx1, 2));
    float s0 = 0.0f, s1 = 0.0f;
    #pragma unroll
    for (int nt = 0; nt < 8; nt++) {
        #pragma unroll
        for (int e = 0; e < 2; e++) {
            acc[nt][e]   = __expf(acc[nt][e]   - mx0); s0 += acc[nt][e];
            acc[nt][2+e] = __expf(acc[nt][2+e] - mx1); s1 += acc[nt][2+e];
        }
    }
    s0 += __shfl_xor_sync(0xffffffffu, s0, 1);
    s0 += __shfl_xor_sync(0xffffffffu, s0, 2);
    s1 += __shfl_xor_sync(0xffffffffu, s1, 1);
    s1 += __shfl_xor_sync(0xffffffffu, s1, 2);
    float inv0 = 1.0f / s0, inv1 = 1.0f / s1;

    // ---- write p fp16 into p_s ----
    #pragma unroll
    for (int nt = 0; nt < 8; nt++) {
        uint32_t wi = (lane & 3) * 4;
        uint32_t a0 = r0*128 + ((uint32_t)(nt ^ (r0&7))<<4) + wi;
        uint32_t a1 = r1*128 + ((uint32_t)(nt ^ (r1&7))<<4) + wi;
        *(uint32_t*)((char*)p_s + a0) = pack_h2(acc[nt][0]*inv0, acc[nt][1]*inv0);
        *(uint32_t*)((char*)p_s + a1) = pack_h2(acc[nt][2]*inv1, acc[nt][3]*inv1);
    }
    __syncwarp();

    // ---- out = p @ v: K=64 (4 ks-steps), 32 cols ----
    float o[4][4];
    #pragma unroll
    for (int nt = 0; nt < 4; nt++)
        #pragma unroll
        for (int q = 0; q < 4; q++) o[nt][q] = 0.0f;

    #pragma unroll
    for (int ks = 0; ks < 4; ks++) {
        int arow = wp*16 + lr8;
        int kc   = 2*ks + lkhi;
        uint32_t a[4];
        LDSM_X4(a[0], a[1], a[2], a[3],
                pb + arow*128 + ((uint32_t)(kc ^ (arow & 7)) << 4));
        uint32_t b[2][4];
        #pragma unroll
        for (int nq = 0; nq < 2; nq++) {
            int brow = nq*16 + lr8;
            LDSM_X4(b[nq][0], b[nq][1], b[nq][2], b[nq][3],
                    vb + brow*128 + ((uint32_t)(kc ^ (brow & 7)) << 4));
        }
        #pragma unroll
        for (int nt = 0; nt < 4; nt++)
            MMA16816(o[nt], a, b[nt>>1][nt&1], b[nt>>1][2+(nt&1)]);
    }

    // ---- scatter out fp16 ----
    #pragma unroll
    for (int s = 0; s < 2; s++) {
        int n = s ? r1 : r0;
        int i = n >> 3, j = n & 7;
        int oh = (wh*8 + i + 4) & 127;
        int ow = (ww*8 + j + 4) & 127;
        size_t tok = (size_t)bimg*16384 + oh*128 + ow;
        __half* base = aoi + tok*256 + head*32;
        #pragma unroll
        for (int nt = 0; nt < 4; nt++) {
            int c = nt*8 + (lane & 3)*2;
            *(uint32_t*)(base + c) = pack_h2(o[nt][s*2], o[nt][s*2+1]);
        }
    }
}

// ---------------------------------------------------------------------------
extern "C" void kernel_launch(void* const* d_in, const int* in_sizes, int n_in,
                              void* d_out, int out_size)
{
    const float* x     = (const float*)d_in[0];
    const float* mask  = (const float*)d_in[1];
    const float* n1g   = (const float*)d_in[2];
    const float* n1b   = (const float*)d_in[3];
    const float* qkvw  = (const float*)d_in[4];
    const float* qkvb  = (const float*)d_in[5];
    const float* relb  = (const float*)d_in[6];
    const float* projw = (const float*)d_in[7];
    const float* projb = (const float*)d_in[8];
    const float* n2g   = (const float*)d_in[9];
    const float* n2b   = (const float*)d_in[10];
    const float* fc1w  = (const float*)d_in[11];
    const float* fc1b  = (const float*)d_in[12];
    const float* fc2w  = (const float*)d_in[13];
    const float* fc2b  = (const float*)d_in[14];
    float* out = (float*)d_out;

    __half *xni, *qkv, *aoi, *hidi, *qkvwi, *projwi, *fc1wi, *fc2wi;
    float *x2;
    cudaGetSymbolAddress((void**)&xni,   g_xni);
    cudaGetSymbolAddress((void**)&qkv,   g_qkv);
    cudaGetSymbolAddress((void**)&aoi,   g_aoi);
    cudaGetSymbolAddress((void**)&x2,    g_x2);
    cudaGetSymbolAddress((void**)&hidi,  g_hidi);
    cudaGetSymbolAddress((void**)&qkvwi, g_qkvwi);
    cudaGetSymbolAddress((void**)&projwi,g_projwi);
    cudaGetSymbolAddress((void**)&fc1wi, g_fc1wi);
    cudaGetSymbolAddress((void**)&fc2wi, g_fc2wi);

    cudaFuncSetAttribute(hgemm<1>, cudaFuncAttributeMaxDynamicSharedMemorySize, HSMEM);
    cudaFuncSetAttribute(hgemm<2>, cudaFuncAttributeMaxDynamicSharedMemorySize, HSMEM);
    cudaFuncSetAttribute(hgemm<3>, cudaFuncAttributeMaxDynamicSharedMemorySize, HSMEM);

    wconv_all<<<768, 256>>>(qkvw, qkvwi, projw, projwi, fc1w, fc1wi, fc2w, fc2wi);

    // 1. LN1 -> fp16
    ln_kernel<<<MT/8, 256>>>(x, n1g, n1b, xni);
    // 2. QKV: [131072,256] @ [768,256]^T -> fp16
    hgemm<3><<<dim3(6, MT/128), 256, HSMEM>>>(xni, qkvwi, qkvb, nullptr, qkv, 768, 256);
    // 3. windowed attention (tensor-core, fp16)
    attn_kernel<<<dim3(8, 2048), 128>>>(qkv, mask, relb, aoi);
    // 4. proj + residual(x) -> x2 fp32
    hgemm<1><<<dim3(2, MT/128), 256, HSMEM>>>(aoi, projwi, projb, x, x2, 256, 256);
    // 5. LN2 -> fp16
    ln_kernel<<<MT/8, 256>>>(x2, n2g, n2b, xni);
    // 6. FC1 + gelu -> fp16 hidden
    hgemm<2><<<dim3(8, MT/128), 256, HSMEM>>>(xni, fc1wi, fc1b, nullptr, hidi, 1024, 256);
    // 7. FC2 + residual(x2) -> out fp32
    hgemm<1><<<dim3(2, MT/128), 256, HSMEM>>>(hidi, fc2wi, fc2b, x2, out, 256, 1024);
}

// round 9
// speedup vs baseline: 1.7360x; 1.0626x over previous
#include <cuda_runtime.h>
#include <cuda_fp16.h>
#include <cstdint>
#include <cmath>

// ===========================================================================
// SwinTransformerBlock on GB300 (family-portable PTX, mma.sync fp16).
// R9: attention — precombined bias+mask table (fp16, smem-staged),
//     v transposed directly in gather, register-resident P (no p_s).
// GEMMs unchanged (at mma.sync HMMA roofline, ~284 TF/s).
// ===========================================================================

#define MT 131072

__device__ __align__(16) __half g_xni [(size_t)MT*256];
__device__ __align__(16) __half g_qkv [(size_t)MT*768];
__device__ __align__(16) __half g_aoi [(size_t)MT*256];
__device__ float                g_x2  [(size_t)MT*256];
__device__ __align__(16) __half g_hidi[(size_t)MT*1024];
__device__ __align__(16) __half g_qkvwi[768*256];
__device__ __align__(16) __half g_projwi[256*256];
__device__ __align__(16) __half g_fc1wi[1024*256];
__device__ __align__(16) __half g_fc2wi[256*1024];
__device__ __align__(16) __half g_cb  [256*8*4096];   // combined bias+mask

// ---------------------------------------------------------------------------
__device__ __forceinline__ uint32_t smem_u32(const void* p) {
    uint32_t a;
    asm("{ .reg .u64 t; cvta.to.shared.u64 t, %1; cvt.u32.u64 %0, t; }" : "=r"(a) : "l"(p));
    return a;
}
#define CP_ASYNC16(sa, ga) \
    asm volatile("cp.async.cg.shared.global [%0], [%1], 16;" :: "r"(sa), "l"(ga))
#define CP_COMMIT() asm volatile("cp.async.commit_group;" ::: "memory")
#define CP_WAIT2()  asm volatile("cp.async.wait_group 2;" ::: "memory")
#define CP_WAIT0()  asm volatile("cp.async.wait_group 0;" ::: "memory")

#define LDSM_X4(r0,r1,r2,r3, a) \
    asm volatile("ldmatrix.sync.aligned.m8n8.x4.shared.b16 {%0,%1,%2,%3}, [%4];" \
        : "=r"(r0), "=r"(r1), "=r"(r2), "=r"(r3) : "r"(a))

#define MMA16816(c, a, b0, b1) \
    asm volatile("mma.sync.aligned.m16n8k16.row.col.f32.f16.f16.f32 " \
        "{%0,%1,%2,%3}, {%4,%5,%6,%7}, {%8,%9}, {%0,%1,%2,%3};" \
        : "+f"((c)[0]), "+f"((c)[1]), "+f"((c)[2]), "+f"((c)[3]) \
        : "r"((a)[0]), "r"((a)[1]), "r"((a)[2]), "r"((a)[3]), "r"(b0), "r"(b1))

__device__ __forceinline__ uint32_t pack_h2(float a, float b) {
    __half2 t = __floats2half2_rn(a, b);
    return *(uint32_t*)&t;
}
__device__ __forceinline__ uint2 pack_h4(float4 v) {
    uint2 u;
    u.x = pack_h2(v.x, v.y);
    u.y = pack_h2(v.z, v.w);
    return u;
}
__device__ __forceinline__ float gelu_f(float v) {
    return 0.5f * v * (1.0f + erff(v * 0.7071067811865476f));
}

// ---------------------------------------------------------------------------
// Combined weight conversion: fp32 [N,K] -> fp16 [N,K]
// ---------------------------------------------------------------------------
__global__ void wconv_all(const float* w0, __half* o0,
                          const float* w1, __half* o1,
                          const float* w2, __half* o2,
                          const float* w3, __half* o3) {
    int i = blockIdx.x * 256 + threadIdx.x;
    const float* w; __half* o; int li;
    if (i < 49152)        { w = w0; o = o0; li = i; }
    else if (i < 65536)   { w = w1; o = o1; li = i - 49152; }
    else if (i < 131072)  { w = w2; o = o2; li = i - 65536; }
    else if (i < 196608)  { w = w3; o = o3; li = i - 131072; }
    else return;
    float4 v = *(const float4*)(w + (size_t)li * 4);
    *(uint2*)(o + (size_t)li * 4) = pack_h4(v);
}

// ---------------------------------------------------------------------------
// Combined bias+mask table: cb[wimg][head][n][m] = bt[relidx(n,m)*8+head]
//                                                 + mask[wimg][n*64+m], fp16
// ---------------------------------------------------------------------------
__global__ void cb_prep(const float* __restrict__ bt, const float* __restrict__ mask,
                        __half* __restrict__ cb) {
    int lin = blockIdx.x * 256 + threadIdx.x;      // half2 index
    int m    = (lin & 31) * 2;
    int n    = (lin >> 5) & 63;
    int head = (lin >> 11) & 7;
    int wimg = lin >> 14;
    float mk0 = mask[wimg*4096 + n*64 + m];
    float mk1 = mask[wimg*4096 + n*64 + m + 1];
    int ri0 = ((n>>3) - (m>>3) + 7)*15 + ((n&7) - (m&7) + 7);
    int ri1 = ((n>>3) - ((m+1)>>3) + 7)*15 + ((n&7) - ((m+1)&7) + 7);
    float b0 = bt[ri0*8 + head] + mk0;
    float b1 = bt[ri1*8 + head] + mk1;
    *(uint32_t*)(cb + (size_t)lin * 2) = pack_h2(b0, b1);
}

// ---------------------------------------------------------------------------
// LayerNorm (C=256): one warp/row, fp16 out [M,256]
// ---------------------------------------------------------------------------
__global__ __launch_bounds__(256) void ln_kernel(
    const float* __restrict__ x, const float* __restrict__ g,
    const float* __restrict__ b, __half* __restrict__ out)
{
    size_t row = (size_t)blockIdx.x * 8 + (threadIdx.x >> 5);
    int lane = threadIdx.x & 31;
    const float* xr = x + row * 256 + lane * 8;
    float4 v0 = *(const float4*)(xr);
    float4 v1 = *(const float4*)(xr + 4);

    float s  = v0.x+v0.y+v0.z+v0.w + v1.x+v1.y+v1.z+v1.w;
    float sq = v0.x*v0.x+v0.y*v0.y+v0.z*v0.z+v0.w*v0.w
             + v1.x*v1.x+v1.y*v1.y+v1.z*v1.z+v1.w*v1.w;
    #pragma unroll
    for (int o = 16; o > 0; o >>= 1) {
        s  += __shfl_xor_sync(0xffffffffu, s,  o);
        sq += __shfl_xor_sync(0xffffffffu, sq, o);
    }
    float mean = s * (1.0f/256.0f);
    float rstd = rsqrtf(sq * (1.0f/256.0f) - mean*mean + 1e-5f);

    const float4 g0 = *(const float4*)(g + lane*8);
    const float4 g1 = *(const float4*)(g + lane*8 + 4);
    const float4 b0 = *(const float4*)(b + lane*8);
    const float4 b1 = *(const float4*)(b + lane*8 + 4);

    float4 o0, o1;
    o0.x=(v0.x-mean)*rstd*g0.x+b0.x; o0.y=(v0.y-mean)*rstd*g0.y+b0.y;
    o0.z=(v0.z-mean)*rstd*g0.z+b0.z; o0.w=(v0.w-mean)*rstd*g0.w+b0.w;
    o1.x=(v1.x-mean)*rstd*g1.x+b1.x; o1.y=(v1.y-mean)*rstd*g1.y+b1.y;
    o1.z=(v1.z-mean)*rstd*g1.z+b1.z; o1.w=(v1.w-mean)*rstd*g1.w+b1.w;

    uint4 u;
    u.x = pack_h2(o0.x, o0.y); u.y = pack_h2(o0.z, o0.w);
    u.z = pack_h2(o1.x, o1.y); u.w = pack_h2(o1.z, o1.w);
    *(uint4*)(out + row * 256 + lane * 8) = u;
}

// ---------------------------------------------------------------------------
// fp16 tensor-core GEMM: CTA 128x128, K-chunk 64, 3-stage cp.async pipeline,
// 256 threads (8 warps 4x2), 2 CTAs/SM.
// MODE: 0=bias fp32; 1=bias+res fp32; 2=bias+gelu fp16; 3=bias fp16.
// ---------------------------------------------------------------------------
#define HSTAGE 32768
#define HSMEM  (3*HSTAGE)

template<int MODE>
__global__ __launch_bounds__(256, 2) void hgemm(
    const __half* __restrict__ A, const __half* __restrict__ B,
    const float* __restrict__ bias, const float* __restrict__ res,
    void* __restrict__ Cout, int N, int K)
{
    extern __shared__ char sm[];
    const uint32_t sbase = smem_u32(sm);
    const int tid  = threadIdx.x;
    const int lane = tid & 31;
    const int warp = tid >> 5;
    const int wr   = warp >> 1;
    const int wc   = warp & 1;
    const size_t gr0 = (size_t)blockIdx.y * 128;
    const int    gc0 = blockIdx.x * 128;
    const int CCH = K >> 6;

    const int lrow = tid >> 3;
    const int lkc  = tid & 7;

    auto load_stage = [&](int c) {
        uint32_t sA = sbase + (c % 3) * HSTAGE;
        uint32_t sB = sA + 16384;
        const __half* Ab = A + c*64 + lkc*8;
        const __half* Bb = B + c*64 + lkc*8;
        #pragma unroll
        for (int p = 0; p < 4; p++) {
            int row = lrow + p*32;
            uint32_t off = row*128 + (((uint32_t)(lkc ^ (row & 7))) << 4);
            CP_ASYNC16(sA + off, Ab + (gr0 + row) * (size_t)K);
            CP_ASYNC16(sB + off, Bb + (size_t)(gc0 + row) * K);
        }
    };

    load_stage(0); CP_COMMIT();
    load_stage(1); CP_COMMIT();

    float acc[2][8][4];
    #pragma unroll
    for (int mt = 0; mt < 2; mt++)
        #pragma unroll
        for (int nt = 0; nt < 8; nt++)
            #pragma unroll
            for (int q = 0; q < 4; q++) acc[mt][nt][q] = 0.0f;

    const int lr8  = (lane & 7) + ((lane >> 3) & 1) * 8;
    const int lkhi = lane >> 4;

    for (int c = 0; c < CCH; c++) {
        if (c + 2 < CCH) { load_stage(c + 2); }
        CP_COMMIT();
        CP_WAIT2();
        __syncthreads();

        uint32_t sA = sbase + (c % 3) * HSTAGE;
        uint32_t sB = sA + 16384;

        #pragma unroll
        for (int ks = 0; ks < 4; ks++) {
            uint32_t a[2][4];
            #pragma unroll
            for (int mt = 0; mt < 2; mt++) {
                int row = wr*32 + mt*16 + lr8;
                int kc  = 2*ks + lkhi;
                LDSM_X4(a[mt][0], a[mt][1], a[mt][2], a[mt][3],
                        sA + row*128 + ((uint32_t)(kc ^ (row & 7)) << 4));
            }
            uint32_t b[4][4];
            #pragma unroll
            for (int nq = 0; nq < 4; nq++) {
                int row = wc*64 + nq*16 + lr8;
                int kc  = 2*ks + lkhi;
                LDSM_X4(b[nq][0], b[nq][1], b[nq][2], b[nq][3],
                        sB + row*128 + ((uint32_t)(kc ^ (row & 7)) << 4));
            }
            #pragma unroll
            for (int mt = 0; mt < 2; mt++)
                #pragma unroll
                for (int nt = 0; nt < 8; nt++)
                    MMA16816(acc[mt][nt], a[mt], b[nt>>1][nt&1], b[nt>>1][2+(nt&1)]);
        }
        __syncthreads();
    }

    // epilogue: stage through smem, coalesced stores
    CP_WAIT0();
    float* epi = (float*)sm;
    const int mrow = lane >> 2;
    const int ncol = (lane & 3) * 2;
    #pragma unroll
    for (int mt = 0; mt < 2; mt++)
        #pragma unroll
        for (int half = 0; half < 2; half++) {
            int r = wr*32 + mt*16 + half*8 + mrow;
            #pragma unroll
            for (int nt = 0; nt < 8; nt++) {
                int cc = wc*64 + nt*8 + ncol;
                *(float2*)&epi[r*132 + cc] =
                    make_float2(acc[mt][nt][half*2], acc[mt][nt][half*2+1]);
            }
        }
    __syncthreads();

    #pragma unroll 4
    for (int it = 0; it < 16; it++) {
        int idx = it*256 + tid;
        int row = idx >> 5;
        int c4  = (idx & 31) * 4;
        int gcol = gc0 + c4;
        float4 v = *(float4*)&epi[row*132 + c4];
        float4 bb = *(const float4*)(bias + gcol);
        v.x += bb.x; v.y += bb.y; v.z += bb.z; v.w += bb.w;
        size_t grow = gr0 + row;
        if (MODE == 1) {
            float4 r = *(const float4*)(res + grow * (size_t)N + gcol);
            v.x += r.x; v.y += r.y; v.z += r.z; v.w += r.w;
        }
        if (MODE == 2) {
            v.x = gelu_f(v.x); v.y = gelu_f(v.y); v.z = gelu_f(v.z); v.w = gelu_f(v.w);
        }
        if (MODE == 2 || MODE == 3) {
            *(uint2*)((__half*)Cout + grow * (size_t)N + gcol) = pack_h4(v);
        } else {
            *(float4*)((float*)Cout + grow * (size_t)N + gcol) = v;
        }
    }
}

// ---------------------------------------------------------------------------
// Fused shifted-window attention via mma.sync fp16.
// One block per (window, head), 128 threads (4 warps).
// qk_s rows: chunks 0-3 = q, 4-7 = k. v_s: [dd][m] (transposed in gather).
// cb_s: combined bias+mask staged from g_cb. P stays in registers.
// ---------------------------------------------------------------------------
__global__ __launch_bounds__(128) void attn_kernel(
    const __half* __restrict__ qkv, const __half* __restrict__ cb,
    __half* __restrict__ aoi)
{
    __shared__ __align__(16) __half qk_s[64*64];   // 8 KB
    __shared__ __align__(16) __half v_s[32*64];    // 4 KB [dd][m]
    __shared__ __align__(16) __half cb_s[64*64];   // 8 KB

    const int head = blockIdx.x;
    const int w    = blockIdx.y;
    const int bimg = w >> 8;
    const int wimg = w & 255;
    const int wh   = wimg >> 4;
    const int ww   = wimg & 15;
    const int tid  = threadIdx.x;
    const int lane = tid & 31;
    const int wp   = tid >> 5;
    const uint32_t qkb = smem_u32(qk_s), vb = smem_u32(v_s);
    const float scale = 0.17677669529663689f;

    // ---- stage combined bias+mask (coalesced, 8KB) ----
    {
        const uint4* src = (const uint4*)(cb + ((size_t)wimg*8 + head)*4096);
        uint4* dst = (uint4*)cb_s;
        #pragma unroll
        for (int i = 0; i < 4; i++) dst[tid + 128*i] = src[tid + 128*i];
    }

    // ---- gather q,k (fp16; scale folded into q) + v transposed ----
    {
        const int dp = (tid & 15) * 2;
        const uint32_t ch = dp >> 3;
        const uint32_t wi = (dp & 7) * 2;
        #pragma unroll
        for (int it = 0; it < 8; it++) {
            int r = (tid >> 4) + 8*it;
            int i = r >> 3, j = r & 7;
            int oh = (wh*8 + i + 4) & 127;
            int ow = (ww*8 + j + 4) & 127;
            size_t tok = (size_t)bimg*16384 + oh*128 + ow;
            const __half* src = qkv + tok*768 + head*32 + dp;
            __half2 qh = *(const __half2*)(src);
            __half2 kh = *(const __half2*)(src + 256);
            __half2 vh = *(const __half2*)(src + 512);
            float2 qf = __half22float2(qh);
            uint32_t qp = pack_h2(qf.x * scale, qf.y * scale);
            uint32_t qa = r*128 + ((ch ^ (uint32_t)(r&7))<<4) + wi;
            uint32_t ka = r*128 + (((ch+4) ^ (uint32_t)(r&7))<<4) + wi;
            *(uint32_t*)((char*)qk_s + qa) = qp;
            *(uint32_t*)((char*)qk_s + ka) = *(uint32_t*)&kh;
            // v transposed: v_s[dd][m] swizzled, 2B stores
            uint32_t va0 = dp*128     + ((uint32_t)((r>>3) ^ (dp&7))    <<4) + (r&7)*2;
            uint32_t va1 = (dp+1)*128 + ((uint32_t)((r>>3) ^ ((dp+1)&7))<<4) + (r&7)*2;
            *(__half*)((char*)v_s + va0) = __low2half(vh);
            *(__half*)((char*)v_s + va1) = __high2half(vh);
        }
    }
    __syncthreads();

    const int lr8  = (lane & 7) + ((lane >> 3) & 1) * 8;
    const int lkhi = lane >> 4;

    // ---- scores: warp wp rows [16wp,16wp+16) x 64, K=32 ----
    float acc[8][4];
    #pragma unroll
    for (int nt = 0; nt < 8; nt++)
        #pragma unroll
        for (int q = 0; q < 4; q++) acc[nt][q] = 0.0f;

    #pragma unroll
    for (int ks = 0; ks < 2; ks++) {
        int arow = wp*16 + lr8;
        int kcq  = 2*ks + lkhi;
        uint32_t a[4];
        LDSM_X4(a[0], a[1], a[2], a[3],
                qkb + arow*128 + ((uint32_t)(kcq ^ (arow & 7)) << 4));
        uint32_t b[4][4];
        #pragma unroll
        for (int nq = 0; nq < 4; nq++) {
            int brow = nq*16 + lr8;
            int kck  = 4 + 2*ks + lkhi;
            LDSM_X4(b[nq][0], b[nq][1], b[nq][2], b[nq][3],
                    qkb + brow*128 + ((uint32_t)(kck ^ (brow & 7)) << 4));
        }
        #pragma unroll
        for (int nt = 0; nt < 8; nt++)
            MMA16816(acc[nt], a, b[nt>>1][nt&1], b[nt>>1][2+(nt&1)]);
    }

    // ---- bias+mask (from smem) + softmax (in-register) ----
    const int r0 = wp*16 + (lane >> 2);
    const int r1 = r0 + 8;
    const int mcol = (lane & 3) * 2;
    float mx0 = -1e30f, mx1 = -1e30f;
    #pragma unroll
    for (int nt = 0; nt < 8; nt++) {
        __half2 c0 = *(__half2*)&cb_s[r0*64 + nt*8 + mcol];
        __half2 c1 = *(__half2*)&cb_s[r1*64 + nt*8 + mcol];
        float2 f0 = __half22float2(c0);
        float2 f1 = __half22float2(c1);
        acc[nt][0] += f0.x; acc[nt][1] += f0.y;
        acc[nt][2] += f1.x; acc[nt][3] += f1.y;
        mx0 = fmaxf(mx0, fmaxf(acc[nt][0], acc[nt][1]));
        mx1 = fmaxf(mx1, fmaxf(acc[nt][2], acc[nt][3]));
    }
    mx0 = fmaxf(mx0, __shfl_xor_sync(0xffffffffu, mx0, 1));
    mx0 = fmaxf(mx0, __shfl_xor_sync(0xffffffffu, mx0, 2));
    mx1 = fmaxf(mx1, __shfl_xor_sync(0xffffffffu, mx1, 1));
    mx1 = fmaxf(mx1, __shfl_xor_sync(0xffffffffu, mx1, 2));
    float s0 = 0.0f, s1 = 0.0f;
    #pragma unroll
    for (int nt = 0; nt < 8; nt++) {
        acc[nt][0] = __expf(acc[nt][0] - mx0); s0 += acc[nt][0];
        acc[nt][1] = __expf(acc[nt][1] - mx0); s0 += acc[nt][1];
        acc[nt][2] = __expf(acc[nt][2] - mx1); s1 += acc[nt][2];
        acc[nt][3] = __expf(acc[nt][3] - mx1); s1 += acc[nt][3];
    }
    s0 += __shfl_xor_sync(0xffffffffu, s0, 1);
    s0 += __shfl_xor_sync(0xffffffffu, s0, 2);
    s1 += __shfl_xor_sync(0xffffffffu, s1, 1);
    s1 += __shfl_xor_sync(0xffffffffu, s1, 2);
    float inv0 = 1.0f / s0, inv1 = 1.0f / s1;

    // ---- out = p @ v: P fragments built directly from score registers ----
    float o[4][4];
    #pragma unroll
    for (int nt = 0; nt < 4; nt++)
        #pragma unroll
        for (int q = 0; q < 4; q++) o[nt][q] = 0.0f;

    #pragma unroll
    for (int kt = 0; kt < 4; kt++) {          // k-tiles of 16 over m=64
        uint32_t a[4];
        a[0] = pack_h2(acc[2*kt][0]*inv0,   acc[2*kt][1]*inv0);
        a[1] = pack_h2(acc[2*kt][2]*inv1,   acc[2*kt][3]*inv1);
        a[2] = pack_h2(acc[2*kt+1][0]*inv0, acc[2*kt+1][1]*inv0);
        a[3] = pack_h2(acc[2*kt+1][2]*inv1, acc[2*kt+1][3]*inv1);
        uint32_t b[2][4];
        #pragma unroll
        for (int nq = 0; nq < 2; nq++) {
            int brow = nq*16 + lr8;
            int kc   = 2*kt + lkhi;
            LDSM_X4(b[nq][0], b[nq][1], b[nq][2], b[nq][3],
                    vb + brow*128 + ((uint32_t)(kc ^ (brow & 7)) << 4));
        }
        #pragma unroll
        for (int nt = 0; nt < 4; nt++)
            MMA16816(o[nt], a, b[nt>>1][nt&1], b[nt>>1][2+(nt&1)]);
    }

    // ---- scatter out fp16 ----
    #pragma unroll
    for (int s = 0; s < 2; s++) {
        int n = s ? r1 : r0;
        int i = n >> 3, j = n & 7;
        int oh = (wh*8 + i + 4) & 127;
        int ow = (ww*8 + j + 4) & 127;
        size_t tok = (size_t)bimg*16384 + oh*128 + ow;
        __half* base = aoi + tok*256 + head*32;
        #pragma unroll
        for (int nt = 0; nt < 4; nt++) {
            int c = nt*8 + (lane & 3)*2;
            *(uint32_t*)(base + c) = pack_h2(o[nt][s*2], o[nt][s*2+1]);
        }
    }
}

// ---------------------------------------------------------------------------
extern "C" void kernel_launch(void* const* d_in, const int* in_sizes, int n_in,
                              void* d_out, int out_size)
{
    const float* x     = (const float*)d_in[0];
    const float* mask  = (const float*)d_in[1];
    const float* n1g   = (const float*)d_in[2];
    const float* n1b   = (const float*)d_in[3];
    const float* qkvw  = (const float*)d_in[4];
    const float* qkvb  = (const float*)d_in[5];
    const float* relb  = (const float*)d_in[6];
    const float* projw = (const float*)d_in[7];
    const float* projb = (const float*)d_in[8];
    const float* n2g   = (const float*)d_in[9];
    const float* n2b   = (const float*)d_in[10];
    const float* fc1w  = (const float*)d_in[11];
    const float* fc1b  = (const float*)d_in[12];
    const float* fc2w  = (const float*)d_in[13];
    const float* fc2b  = (const float*)d_in[14];
    float* out = (float*)d_out;

    __half *xni, *qkv, *aoi, *hidi, *qkvwi, *projwi, *fc1wi, *fc2wi, *cb;
    float *x2;
    cudaGetSymbolAddress((void**)&xni,   g_xni);
    cudaGetSymbolAddress((void**)&qkv,   g_qkv);
    cudaGetSymbolAddress((void**)&aoi,   g_aoi);
    cudaGetSymbolAddress((void**)&x2,    g_x2);
    cudaGetSymbolAddress((void**)&hidi,  g_hidi);
    cudaGetSymbolAddress((void**)&qkvwi, g_qkvwi);
    cudaGetSymbolAddress((void**)&projwi,g_projwi);
    cudaGetSymbolAddress((void**)&fc1wi, g_fc1wi);
    cudaGetSymbolAddress((void**)&fc2wi, g_fc2wi);
    cudaGetSymbolAddress((void**)&cb,    g_cb);

    cudaFuncSetAttribute(hgemm<1>, cudaFuncAttributeMaxDynamicSharedMemorySize, HSMEM);
    cudaFuncSetAttribute(hgemm<2>, cudaFuncAttributeMaxDynamicSharedMemorySize, HSMEM);
    cudaFuncSetAttribute(hgemm<3>, cudaFuncAttributeMaxDynamicSharedMemorySize, HSMEM);

    wconv_all<<<768, 256>>>(qkvw, qkvwi, projw, projwi, fc1w, fc1wi, fc2w, fc2wi);
    cb_prep<<<16384, 256>>>(relb, mask, cb);

    // 1. LN1 -> fp16
    ln_kernel<<<MT/8, 256>>>(x, n1g, n1b, xni);
    // 2. QKV: [131072,256] @ [768,256]^T -> fp16
    hgemm<3><<<dim3(6, MT/128), 256, HSMEM>>>(xni, qkvwi, qkvb, nullptr, qkv, 768, 256);
    // 3. windowed attention (tensor-core, fp16)
    attn_kernel<<<dim3(8, 2048), 128>>>(qkv, cb, aoi);
    // 4. proj + residual(x) -> x2 fp32
    hgemm<1><<<dim3(2, MT/128), 256, HSMEM>>>(aoi, projwi, projb, x, x2, 256, 256);
    // 5. LN2 -> fp16
    ln_kernel<<<MT/8, 256>>>(x2, n2g, n2b, xni);
    // 6. FC1 + gelu -> fp16 hidden
    hgemm<2><<<dim3(8, MT/128), 256, HSMEM>>>(xni, fc1wi, fc1b, nullptr, hidi, 1024, 256);
    // 7. FC2 + residual(x2) -> out fp32
    hgemm<1><<<dim3(2, MT/128), 256, HSMEM>>>(hidi, fc2wi, fc2b, x2, out, 256, 1024);
}